// round 1
// baseline (speedup 1.0000x reference)
#include <cuda_runtime.h>
#include <cuda_bf16.h>
#include <cstdint>

// Problem constants
#define B_  2
#define L_  512
#define D_  1024
#define E_  32      // INNER
#define P_  128     // PAIR

// Scratch for q, k (allocation-free rule: __device__ globals)
__device__ float g_q[B_ * L_ * E_];   // [b*L + j][e]
__device__ float g_k[B_ * L_ * E_];   // [b*L + i][e]

// ---------------------------------------------------------------------------
// packed f32x2 helpers
// ---------------------------------------------------------------------------
__device__ __forceinline__ void fma2(unsigned long long& d,
                                     unsigned long long a,
                                     unsigned long long b) {
    asm("fma.rn.f32x2 %0, %1, %2, %0;" : "+l"(d) : "l"(a), "l"(b));
}
__device__ __forceinline__ unsigned long long pack2(float x, float y) {
    unsigned long long r;
    asm("mov.b64 %0, {%1, %2};" : "=l"(r) : "f"(x), "f"(y));
    return r;
}
__device__ __forceinline__ void unpack2(unsigned long long v, float& lo, float& hi) {
    asm("mov.b64 {%0, %1}, %2;" : "=f"(lo), "=f"(hi) : "l"(v));
}
__device__ __forceinline__ float f4_elem(const float4& v, int i) {
    switch (i) {
        case 0: return v.x;
        case 1: return v.y;
        case 2: return v.z;
        default: return v.w;
    }
}

// ---------------------------------------------------------------------------
// Kernel 1: LayerNorm + projection  ->  q, k   (1024 blocks x 256 threads)
// ---------------------------------------------------------------------------
__global__ __launch_bounds__(256)
void ln_proj_kernel(const float* __restrict__ x,
                    const float* __restrict__ gamma,
                    const float* __restrict__ beta,
                    const float* __restrict__ Wp,   // [64][1024]
                    const float* __restrict__ bp) { // [64]
    const int row = blockIdx.x;                 // b*L + l
    const int tid = threadIdx.x;
    __shared__ float sn[D_];
    __shared__ float red[8];
    __shared__ float s_mean, s_rs;

    const float* xr = x + (size_t)row * D_;
    float4 xv = reinterpret_cast<const float4*>(xr)[tid];

    // mean
    float s = xv.x + xv.y + xv.z + xv.w;
    #pragma unroll
    for (int o = 16; o > 0; o >>= 1) s += __shfl_xor_sync(0xffffffffu, s, o);
    if ((tid & 31) == 0) red[tid >> 5] = s;
    __syncthreads();
    if (tid == 0) {
        float t = 0.f;
        #pragma unroll
        for (int w = 0; w < 8; w++) t += red[w];
        s_mean = t * (1.0f / D_);
    }
    __syncthreads();
    const float mu = s_mean;

    // variance
    float d0 = xv.x - mu, d1 = xv.y - mu, d2 = xv.z - mu, d3 = xv.w - mu;
    float ss = d0 * d0 + d1 * d1 + d2 * d2 + d3 * d3;
    #pragma unroll
    for (int o = 16; o > 0; o >>= 1) ss += __shfl_xor_sync(0xffffffffu, ss, o);
    if ((tid & 31) == 0) red[tid >> 5] = ss;
    __syncthreads();
    if (tid == 0) {
        float t = 0.f;
        #pragma unroll
        for (int w = 0; w < 8; w++) t += red[w];
        s_rs = rsqrtf(t * (1.0f / D_) + 1e-5f);
    }
    __syncthreads();
    const float rs = s_rs;

    // normalize (apply gamma/beta)
    {
        float4 g = reinterpret_cast<const float4*>(gamma)[tid];
        float4 be = reinterpret_cast<const float4*>(beta)[tid];
        float4 o4;
        o4.x = d0 * rs * g.x + be.x;
        o4.y = d1 * rs * g.y + be.y;
        o4.z = d2 * rs * g.z + be.z;
        o4.w = d3 * rs * g.w + be.w;
        reinterpret_cast<float4*>(sn)[tid] = o4;
    }
    __syncthreads();

    // projection: 64 outputs, 4 threads each
    const int o = tid >> 2;
    const int part = tid & 3;
    const float4* w4 = reinterpret_cast<const float4*>(Wp + (size_t)o * D_);
    const float4* s4 = reinterpret_cast<const float4*>(sn);
    float acc = 0.f;
    #pragma unroll 8
    for (int t = 0; t < 64; t++) {
        int f = part + 4 * t;
        float4 a = s4[f];
        float4 w = w4[f];
        acc += a.x * w.x + a.y * w.y + a.z * w.z + a.w * w.w;
    }
    acc += __shfl_xor_sync(0xffffffffu, acc, 1);
    acc += __shfl_xor_sync(0xffffffffu, acc, 2);
    if (part == 0) {
        acc += bp[o];
        if (o < E_) g_q[(size_t)row * E_ + o] = acc;
        else        g_k[(size_t)row * E_ + (o - E_)] = acc;
    }
}

// ---------------------------------------------------------------------------
// Kernel 2: per-(b,i) tile: out[i, :, :] = Q(512x32) @ M_i(32x128) + C_i
//   M_i[e][p] = W_o[p][e]*k[i][e] + W_o[p][32+e]
//   C_i[p]    = b_o[p] - sum_e W_o[p][32+e]*k[i][e]
// 1024 blocks x 256 threads. Register tile: 4 j-rows x 16 p-cols (f32x2 packed)
// ---------------------------------------------------------------------------
#define QPAD 36   // padded Q row stride (floats): 4-row stride = 144B -> disjoint bank spans

__global__ __launch_bounds__(256, 2)
void pair_kernel(const float* __restrict__ Wo,   // [128][64]
                 const float* __restrict__ bo,   // [128]
                 float* __restrict__ out) {      // [B][L][L][P]
    const int bi = blockIdx.x;        // b*L + i
    const int b  = bi >> 9;
    const int tid = threadIdx.x;
    const int tx = tid & 7;           // p-group
    const int ty = tid >> 3;          // 0..31, j-row base

    __shared__ float sK[E_];
    __shared__ float sC[P_];
    __shared__ float sM[E_ * P_];     // [e][p], 16 KB
    __shared__ float sQ[128 * QPAD];  // one 128-row j chunk, padded

    if (tid < E_) sK[tid] = g_k[(size_t)bi * E_ + tid];
    __syncthreads();

    if (tid < P_) {
        const int p = tid;
        const float* wrow = Wo + (size_t)p * (2 * E_);
        float c = bo[p];
        #pragma unroll
        for (int e = 0; e < E_; e++) {
            float w1 = wrow[e];
            float w2 = wrow[E_ + e];
            sM[e * P_ + p] = w1 * sK[e] + w2;
            c -= w2 * sK[e];
        }
        sC[p] = c;
    }

    const float* qbase = g_q + (size_t)b * L_ * E_;

    for (int c = 0; c < 4; c++) {
        __syncthreads();   // protect sQ from previous chunk readers (also fences sM/sC setup at c=0)
        // stage 128 rows of q: 2 threads per row, 16 floats each
        {
            const int row  = tid >> 1;
            const int half = tid & 1;
            const float4* src = reinterpret_cast<const float4*>(
                qbase + (size_t)(c * 128 + row) * E_ + half * 16);
            float4* dst = reinterpret_cast<float4*>(&sQ[row * QPAD + half * 16]);
            #pragma unroll
            for (int kk = 0; kk < 4; kk++) dst[kk] = src[kk];
        }
        __syncthreads();

        unsigned long long acc[4][8];
        #pragma unroll
        for (int r = 0; r < 4; r++)
            #pragma unroll
            for (int m = 0; m < 8; m++) acc[r][m] = 0ull;

        #pragma unroll
        for (int e0 = 0; e0 < E_; e0 += 4) {
            float4 qv0 = *reinterpret_cast<const float4*>(&sQ[(ty +  0) * QPAD + e0]);
            float4 qv1 = *reinterpret_cast<const float4*>(&sQ[(ty + 32) * QPAD + e0]);
            float4 qv2 = *reinterpret_cast<const float4*>(&sQ[(ty + 64) * QPAD + e0]);
            float4 qv3 = *reinterpret_cast<const float4*>(&sQ[(ty + 96) * QPAD + e0]);
            #pragma unroll
            for (int ee = 0; ee < 4; ee++) {
                const int e = e0 + ee;
                const float* mrow = &sM[e * P_];
                ulonglong2 b0 = *reinterpret_cast<const ulonglong2*>(mrow + (tx +  0) * 4);
                ulonglong2 b1 = *reinterpret_cast<const ulonglong2*>(mrow + (tx +  8) * 4);
                ulonglong2 b2 = *reinterpret_cast<const ulonglong2*>(mrow + (tx + 16) * 4);
                ulonglong2 b3 = *reinterpret_cast<const ulonglong2*>(mrow + (tx + 24) * 4);
                unsigned long long a0 = pack2(f4_elem(qv0, ee), f4_elem(qv0, ee));
                unsigned long long a1 = pack2(f4_elem(qv1, ee), f4_elem(qv1, ee));
                unsigned long long a2 = pack2(f4_elem(qv2, ee), f4_elem(qv2, ee));
                unsigned long long a3 = pack2(f4_elem(qv3, ee), f4_elem(qv3, ee));
                fma2(acc[0][0], a0, b0.x); fma2(acc[0][1], a0, b0.y);
                fma2(acc[0][2], a0, b1.x); fma2(acc[0][3], a0, b1.y);
                fma2(acc[0][4], a0, b2.x); fma2(acc[0][5], a0, b2.y);
                fma2(acc[0][6], a0, b3.x); fma2(acc[0][7], a0, b3.y);
                fma2(acc[1][0], a1, b0.x); fma2(acc[1][1], a1, b0.y);
                fma2(acc[1][2], a1, b1.x); fma2(acc[1][3], a1, b1.y);
                fma2(acc[1][4], a1, b2.x); fma2(acc[1][5], a1, b2.y);
                fma2(acc[1][6], a1, b3.x); fma2(acc[1][7], a1, b3.y);
                fma2(acc[2][0], a2, b0.x); fma2(acc[2][1], a2, b0.y);
                fma2(acc[2][2], a2, b1.x); fma2(acc[2][3], a2, b1.y);
                fma2(acc[2][4], a2, b2.x); fma2(acc[2][5], a2, b2.y);
                fma2(acc[2][6], a2, b3.x); fma2(acc[2][7], a2, b3.y);
                fma2(acc[3][0], a3, b0.x); fma2(acc[3][1], a3, b0.y);
                fma2(acc[3][2], a3, b1.x); fma2(acc[3][3], a3, b1.y);
                fma2(acc[3][4], a3, b2.x); fma2(acc[3][5], a3, b2.y);
                fma2(acc[3][6], a3, b3.x); fma2(acc[3][7], a3, b3.y);
            }
        }

        // epilogue: add C, store float4 per (r, m)
        #pragma unroll
        for (int r = 0; r < 4; r++) {
            const int j = c * 128 + ty + 32 * r;
            float* orow = out + (((size_t)bi) * L_ + j) * P_;
            #pragma unroll
            for (int m = 0; m < 4; m++) {
                const int p0 = (tx + 8 * m) * 4;
                float lo0, hi0, lo1, hi1;
                unpack2(acc[r][2 * m + 0], lo0, hi0);
                unpack2(acc[r][2 * m + 1], lo1, hi1);
                float4 cv = *reinterpret_cast<const float4*>(&sC[p0]);
                float4 o4;
                o4.x = lo0 + cv.x;
                o4.y = hi0 + cv.y;
                o4.z = lo1 + cv.z;
                o4.w = hi1 + cv.w;
                *reinterpret_cast<float4*>(orow + p0) = o4;
            }
        }
    }
}

// ---------------------------------------------------------------------------
// launch
// ---------------------------------------------------------------------------
extern "C" void kernel_launch(void* const* d_in, const int* in_sizes, int n_in,
                              void* d_out, int out_size) {
    const float* seq   = (const float*)d_in[0];
    const float* gamma = (const float*)d_in[1];
    const float* beta  = (const float*)d_in[2];
    const float* Wp    = (const float*)d_in[3];
    const float* bp    = (const float*)d_in[4];
    const float* Wo    = (const float*)d_in[5];
    const float* bo    = (const float*)d_in[6];
    float* out = (float*)d_out;

    ln_proj_kernel<<<B_ * L_, 256>>>(seq, gamma, beta, Wp, bp);
    pair_kernel<<<B_ * L_, 256>>>(Wo, bo, out);
}

// round 3
// speedup vs baseline: 1.3110x; 1.3110x over previous
#include <cuda_runtime.h>
#include <cuda_bf16.h>
#include <cstdint>

#define B_  2
#define L_  512
#define D_  1024
#define E_  32      // INNER
#define P_  128     // PAIR

// Scratch for q, k (allocation-free rule: __device__ globals)
__device__ float g_q[B_ * L_ * E_];   // [b*L + j][e]
__device__ float g_k[B_ * L_ * E_];   // [b*L + i][e]

// ---------------------------------------------------------------------------
// helpers
// ---------------------------------------------------------------------------
__device__ __forceinline__ void mma_bf16(float& d0, float& d1, float& d2, float& d3,
                                         uint32_t a0, uint32_t a1, uint32_t b0) {
    asm volatile(
        "mma.sync.aligned.m16n8k8.row.col.f32.bf16.bf16.f32 "
        "{%0,%1,%2,%3}, {%4,%5}, {%6}, {%0,%1,%2,%3};"
        : "+f"(d0), "+f"(d1), "+f"(d2), "+f"(d3)
        : "r"(a0), "r"(a1), "r"(b0));
}

// bf16 hi/lo split of two floats, packed into two words (lo element in low half)
__device__ __forceinline__ void split2(float a, float b, uint32_t& hw, uint32_t& lw) {
    __nv_bfloat16 ah = __float2bfloat16(a);
    __nv_bfloat16 bh = __float2bfloat16(b);
    __nv_bfloat16 al = __float2bfloat16(a - __bfloat162float(ah));
    __nv_bfloat16 bl = __float2bfloat16(b - __bfloat162float(bh));
    hw = (uint32_t)__bfloat16_as_ushort(ah) | ((uint32_t)__bfloat16_as_ushort(bh) << 16);
    lw = (uint32_t)__bfloat16_as_ushort(al) | ((uint32_t)__bfloat16_as_ushort(bl) << 16);
}

// ---------------------------------------------------------------------------
// Kernel 1: LayerNorm + projection -> q, k
// 128 blocks x 256 threads, warp-per-row LN, 8 rows per CTA (W reused 8x)
// ---------------------------------------------------------------------------
__global__ __launch_bounds__(256)
void ln_proj_kernel(const float* __restrict__ x,
                    const float* __restrict__ gamma,
                    const float* __restrict__ beta,
                    const float* __restrict__ Wp,   // [64][1024]
                    const float* __restrict__ bp) { // [64]
    const int tid = threadIdx.x;
    const int wid = tid >> 5;
    const int lid = tid & 31;
    const int row = blockIdx.x * 8 + wid;

    __shared__ float sn[8][D_];

    {
        const float4* xr = reinterpret_cast<const float4*>(x + (size_t)row * D_);
        float4 v[8];
        #pragma unroll
        for (int u = 0; u < 8; u++) v[u] = xr[lid + 32 * u];

        float s = 0.f;
        #pragma unroll
        for (int u = 0; u < 8; u++) s += v[u].x + v[u].y + v[u].z + v[u].w;
        #pragma unroll
        for (int o = 16; o > 0; o >>= 1) s += __shfl_xor_sync(0xffffffffu, s, o);
        const float mu = s * (1.0f / D_);

        float ss = 0.f;
        #pragma unroll
        for (int u = 0; u < 8; u++) {
            float d0 = v[u].x - mu, d1 = v[u].y - mu, d2 = v[u].z - mu, d3 = v[u].w - mu;
            ss += d0 * d0 + d1 * d1 + d2 * d2 + d3 * d3;
        }
        #pragma unroll
        for (int o = 16; o > 0; o >>= 1) ss += __shfl_xor_sync(0xffffffffu, ss, o);
        const float rs = rsqrtf(ss * (1.0f / D_) + 1e-5f);

        const float4* g4 = reinterpret_cast<const float4*>(gamma);
        const float4* b4 = reinterpret_cast<const float4*>(beta);
        #pragma unroll
        for (int u = 0; u < 8; u++) {
            float4 g = g4[lid + 32 * u];
            float4 be = b4[lid + 32 * u];
            float4 o4;
            o4.x = (v[u].x - mu) * rs * g.x + be.x;
            o4.y = (v[u].y - mu) * rs * g.y + be.y;
            o4.z = (v[u].z - mu) * rs * g.z + be.z;
            o4.w = (v[u].w - mu) * rs * g.w + be.w;
            reinterpret_cast<float4*>(sn[wid])[lid + 32 * u] = o4;
        }
    }
    __syncthreads();

    const int o = tid >> 2;
    const int part = tid & 3;
    const float4* w4 = reinterpret_cast<const float4*>(Wp + (size_t)o * D_);
    float acc[8];
    #pragma unroll
    for (int r = 0; r < 8; r++) acc[r] = 0.f;

    #pragma unroll 4
    for (int t = 0; t < 64; t++) {
        const int f = part + 4 * t;
        float4 w = w4[f];
        #pragma unroll
        for (int r = 0; r < 8; r++) {
            float4 a = reinterpret_cast<const float4*>(sn[r])[f];
            acc[r] += a.x * w.x + a.y * w.y + a.z * w.z + a.w * w.w;
        }
    }
    #pragma unroll
    for (int r = 0; r < 8; r++) {
        acc[r] += __shfl_xor_sync(0xffffffffu, acc[r], 1);
        acc[r] += __shfl_xor_sync(0xffffffffu, acc[r], 2);
    }
    if (part == 0) {
        const float bias = bp[o];
        const int row0 = blockIdx.x * 8;
        #pragma unroll
        for (int r = 0; r < 8; r++) {
            float val = acc[r] + bias;
            if (o < E_) g_q[(size_t)(row0 + r) * E_ + o] = val;
            else        g_k[(size_t)(row0 + r) * E_ + (o - E_)] = val;
        }
    }
}

// ---------------------------------------------------------------------------
// Kernel 2: warp-level HMMA path.
// Per CTA (b,i): D(512x128) = Q(512x32) @ M_i^T(128x32) + C_i
//   M_i[p][e] = Wo[p][e]*k[i][e] + Wo[p][32+e]
//   C_i[p]    = bo[p] - sum_e Wo[p][32+e]*k[i][e]
// bf16 3-split (QhMh + QhMl + QlMh), fp32 accum via mma.sync m16n8k8.
// Rows padded to 80B so all fragment lds are conflict-free.
// ---------------------------------------------------------------------------
#define ROWB 80   // bytes per padded row (32 bf16 data + pad)

#define OFF_SK  0                       // 32 f
#define OFF_SC  128                     // 128 f
#define OFF_QH  640                     // 512 * 80
#define OFF_QL  (OFF_QH + 512 * ROWB)   // 41600
#define OFF_MH  (OFF_QL + 512 * ROWB)   // 82560, 128 * 80
#define OFF_ML  (OFF_MH + 128 * ROWB)   // 92800
#define SMEM_TOTAL (OFF_ML + 128 * ROWB) // 103040

__global__ __launch_bounds__(256, 1)
void pair_mma_kernel(const float* __restrict__ Wo,   // [128][64]
                     const float* __restrict__ bo,   // [128]
                     float* __restrict__ out) {      // [B][L][L][P]
    extern __shared__ char smem[];
    float* sK = reinterpret_cast<float*>(smem + OFF_SK);
    float* sC = reinterpret_cast<float*>(smem + OFF_SC);
    char* qh = smem + OFF_QH;
    char* ql = smem + OFF_QL;
    char* mh = smem + OFF_MH;
    char* ml = smem + OFF_ML;

    const int bi = blockIdx.x;        // b*L + i
    const int b  = bi >> 9;
    const int tid = threadIdx.x;
    const int wid = tid >> 5;
    const int lid = tid & 31;

    if (tid < E_) sK[tid] = g_k[(size_t)bi * E_ + tid];
    __syncthreads();

    // --- build M (bf16 hi/lo, [p][e] n-major) + C: thread = (p, halfe) ---
    {
        const int p = tid >> 1;
        const int halfe = tid & 1;
        const float* wrow = Wo + (size_t)p * (2 * E_);
        float m[16];
        float cacc = 0.f;
        #pragma unroll
        for (int u = 0; u < 16; u++) {
            const int e = halfe * 16 + u;
            float w1 = wrow[e];
            float w2 = wrow[E_ + e];
            float kv = sK[e];
            m[u] = fmaf(w1, kv, w2);
            cacc += w2 * kv;
        }
        float other = __shfl_xor_sync(0xffffffffu, cacc, 1);
        if (halfe == 0) sC[p] = bo[p] - (cacc + other);

        #pragma unroll
        for (int g = 0; g < 2; g++) {
            uint32_t hw[4], lw[4];
            #pragma unroll
            for (int q = 0; q < 4; q++)
                split2(m[g * 8 + 2 * q], m[g * 8 + 2 * q + 1], hw[q], lw[q]);
            const uint32_t off = (uint32_t)p * ROWB + (uint32_t)halfe * 32u + (uint32_t)g * 16u;
            *reinterpret_cast<uint4*>(mh + off) = make_uint4(hw[0], hw[1], hw[2], hw[3]);
            *reinterpret_cast<uint4*>(ml + off) = make_uint4(lw[0], lw[1], lw[2], lw[3]);
        }
    }

    // --- stage Q (bf16 hi/lo, [j][e]) ---
    {
        const float* qbase = g_q + (size_t)b * L_ * E_;
        #pragma unroll
        for (int it = 0; it < 8; it++) {
            const int idx = tid + 256 * it;           // 0..2047
            const int row = idx >> 2;
            const int grp = idx & 3;                  // e0 = grp*8
            const float4* src = reinterpret_cast<const float4*>(
                qbase + (size_t)row * E_ + grp * 8);
            float4 v0 = src[0];
            float4 v1 = src[1];
            uint32_t hw[4], lw[4];
            split2(v0.x, v0.y, hw[0], lw[0]);
            split2(v0.z, v0.w, hw[1], lw[1]);
            split2(v1.x, v1.y, hw[2], lw[2]);
            split2(v1.z, v1.w, hw[3], lw[3]);
            const uint32_t off = (uint32_t)row * ROWB + (uint32_t)grp * 16u;
            *reinterpret_cast<uint2*>(qh + off)     = make_uint2(hw[0], hw[1]);
            *reinterpret_cast<uint2*>(qh + off + 8) = make_uint2(hw[2], hw[3]);
            *reinterpret_cast<uint2*>(ql + off)     = make_uint2(lw[0], lw[1]);
            *reinterpret_cast<uint2*>(ql + off + 8) = make_uint2(lw[2], lw[3]);
        }
    }

    __syncthreads();

    // --- compute: warp w -> j rows [w*64, w*64+64); loop p-halves of 64 ---
    const int j0 = wid * 64;
    const int g   = lid >> 2;   // groupID 0..7
    const int tig = lid & 3;    // thread-in-group

    const char* Abase[3] = { qh, qh, ql };
    const char* Bbase[3] = { mh, ml, mh };

    #pragma unroll 1
    for (int h = 0; h < 2; h++) {
        float acc[4][8][4];
        #pragma unroll
        for (int mi = 0; mi < 4; mi++)
            #pragma unroll
            for (int ni = 0; ni < 8; ni++)
                #pragma unroll
                for (int q = 0; q < 4; q++) acc[mi][ni][q] = 0.f;

        #pragma unroll
        for (int s = 0; s < 3; s++) {
            const char* A = Abase[s];
            const char* Bb = Bbase[s];
            #pragma unroll
            for (int ks = 0; ks < 4; ks++) {
                const uint32_t kb = (uint32_t)(ks * 8 + 2 * tig) * 2u;  // byte offset of k-pair
                uint32_t a0[4], a1[4];
                #pragma unroll
                for (int mi = 0; mi < 4; mi++) {
                    const uint32_t r = (uint32_t)(j0 + mi * 16 + g);
                    a0[mi] = *reinterpret_cast<const uint32_t*>(A + r * ROWB + kb);
                    a1[mi] = *reinterpret_cast<const uint32_t*>(A + (r + 8) * ROWB + kb);
                }
                uint32_t bb[8];
                #pragma unroll
                for (int ni = 0; ni < 8; ni++) {
                    const uint32_t n = (uint32_t)(h * 64 + ni * 8 + g);
                    bb[ni] = *reinterpret_cast<const uint32_t*>(Bb + n * ROWB + kb);
                }
                #pragma unroll
                for (int mi = 0; mi < 4; mi++)
                    #pragma unroll
                    for (int ni = 0; ni < 8; ni++)
                        mma_bf16(acc[mi][ni][0], acc[mi][ni][1],
                                 acc[mi][ni][2], acc[mi][ni][3],
                                 a0[mi], a1[mi], bb[ni]);
            }
        }

        // --- epilogue: add C, store ---
        #pragma unroll
        for (int mi = 0; mi < 4; mi++) {
            const int j = j0 + mi * 16 + g;
            float* orow0 = out + (((size_t)bi) * L_ + j) * P_;
            float* orow1 = orow0 + 8 * P_;
            #pragma unroll
            for (int ni = 0; ni < 8; ni++) {
                const int p = h * 64 + ni * 8 + 2 * tig;
                float2 cv = *reinterpret_cast<const float2*>(sC + p);
                float2 o0, o1;
                o0.x = acc[mi][ni][0] + cv.x;
                o0.y = acc[mi][ni][1] + cv.y;
                o1.x = acc[mi][ni][2] + cv.x;
                o1.y = acc[mi][ni][3] + cv.y;
                *reinterpret_cast<float2*>(orow0 + p) = o0;
                *reinterpret_cast<float2*>(orow1 + p) = o1;
            }
        }
    }
}

// ---------------------------------------------------------------------------
// launch
// ---------------------------------------------------------------------------
extern "C" void kernel_launch(void* const* d_in, const int* in_sizes, int n_in,
                              void* d_out, int out_size) {
    const float* seq   = (const float*)d_in[0];
    const float* gamma = (const float*)d_in[1];
    const float* beta  = (const float*)d_in[2];
    const float* Wp    = (const float*)d_in[3];
    const float* bp    = (const float*)d_in[4];
    const float* Wo    = (const float*)d_in[5];
    const float* bo    = (const float*)d_in[6];
    float* out = (float*)d_out;

    static int smem_set = 0;
    if (!smem_set) {
        cudaFuncSetAttribute(pair_mma_kernel,
                             cudaFuncAttributeMaxDynamicSharedMemorySize, SMEM_TOTAL);
        smem_set = 1;
    }

    ln_proj_kernel<<<128, 256>>>(seq, gamma, beta, Wp, bp);
    pair_mma_kernel<<<B_ * L_, 256, SMEM_TOTAL>>>(Wo, bo, out);
}

// round 4
// speedup vs baseline: 1.3809x; 1.0533x over previous
#include <cuda_runtime.h>
#include <cuda_bf16.h>
#include <cstdint>

#define B_  2
#define L_  512
#define D_  1024
#define E_  32      // INNER
#define P_  128     // PAIR

// Scratch for q, k (allocation-free rule: __device__ globals)
__device__ float g_q[B_ * L_ * E_];   // [b*L + j][e]
__device__ float g_k[B_ * L_ * E_];   // [b*L + i][e]

// ---------------------------------------------------------------------------
// helpers
// ---------------------------------------------------------------------------
__device__ __forceinline__ void mma_bf16(float& d0, float& d1, float& d2, float& d3,
                                         uint32_t a0, uint32_t a1, uint32_t b0) {
    asm volatile(
        "mma.sync.aligned.m16n8k8.row.col.f32.bf16.bf16.f32 "
        "{%0,%1,%2,%3}, {%4,%5}, {%6}, {%0,%1,%2,%3};"
        : "+f"(d0), "+f"(d1), "+f"(d2), "+f"(d3)
        : "r"(a0), "r"(a1), "r"(b0));
}

// bf16 hi/lo split of two floats, packed into two words
__device__ __forceinline__ void split2(float a, float b, uint32_t& hw, uint32_t& lw) {
    __nv_bfloat16 ah = __float2bfloat16(a);
    __nv_bfloat16 bh = __float2bfloat16(b);
    __nv_bfloat16 al = __float2bfloat16(a - __bfloat162float(ah));
    __nv_bfloat16 bl = __float2bfloat16(b - __bfloat162float(bh));
    hw = (uint32_t)__bfloat16_as_ushort(ah) | ((uint32_t)__bfloat16_as_ushort(bh) << 16);
    lw = (uint32_t)__bfloat16_as_ushort(al) | ((uint32_t)__bfloat16_as_ushort(bl) << 16);
}

// ---------------------------------------------------------------------------
// Kernel 1: LayerNorm + projection -> q, k
// 128 blocks x 256 threads, warp-per-row LN, 8 rows per CTA (W reused 8x)
// ---------------------------------------------------------------------------
__global__ __launch_bounds__(256)
void ln_proj_kernel(const float* __restrict__ x,
                    const float* __restrict__ gamma,
                    const float* __restrict__ beta,
                    const float* __restrict__ Wp,   // [64][1024]
                    const float* __restrict__ bp) { // [64]
    const int tid = threadIdx.x;
    const int wid = tid >> 5;
    const int lid = tid & 31;
    const int row = blockIdx.x * 8 + wid;

    __shared__ float sn[8][D_];

    {
        const float4* xr = reinterpret_cast<const float4*>(x + (size_t)row * D_);
        float4 v[8];
        #pragma unroll
        for (int u = 0; u < 8; u++) v[u] = xr[lid + 32 * u];

        float s = 0.f;
        #pragma unroll
        for (int u = 0; u < 8; u++) s += v[u].x + v[u].y + v[u].z + v[u].w;
        #pragma unroll
        for (int o = 16; o > 0; o >>= 1) s += __shfl_xor_sync(0xffffffffu, s, o);
        const float mu = s * (1.0f / D_);

        float ss = 0.f;
        #pragma unroll
        for (int u = 0; u < 8; u++) {
            float d0 = v[u].x - mu, d1 = v[u].y - mu, d2 = v[u].z - mu, d3 = v[u].w - mu;
            ss += d0 * d0 + d1 * d1 + d2 * d2 + d3 * d3;
        }
        #pragma unroll
        for (int o = 16; o > 0; o >>= 1) ss += __shfl_xor_sync(0xffffffffu, ss, o);
        const float rs = rsqrtf(ss * (1.0f / D_) + 1e-5f);

        const float4* g4 = reinterpret_cast<const float4*>(gamma);
        const float4* b4 = reinterpret_cast<const float4*>(beta);
        #pragma unroll
        for (int u = 0; u < 8; u++) {
            float4 g = g4[lid + 32 * u];
            float4 be = b4[lid + 32 * u];
            float4 o4;
            o4.x = (v[u].x - mu) * rs * g.x + be.x;
            o4.y = (v[u].y - mu) * rs * g.y + be.y;
            o4.z = (v[u].z - mu) * rs * g.z + be.z;
            o4.w = (v[u].w - mu) * rs * g.w + be.w;
            reinterpret_cast<float4*>(sn[wid])[lid + 32 * u] = o4;
        }
    }
    __syncthreads();

    const int o = tid >> 2;
    const int part = tid & 3;
    const float4* w4 = reinterpret_cast<const float4*>(Wp + (size_t)o * D_);
    float acc[8];
    #pragma unroll
    for (int r = 0; r < 8; r++) acc[r] = 0.f;

    #pragma unroll 4
    for (int t = 0; t < 64; t++) {
        const int f = part + 4 * t;
        float4 w = w4[f];
        #pragma unroll
        for (int r = 0; r < 8; r++) {
            float4 a = reinterpret_cast<const float4*>(sn[r])[f];
            acc[r] += a.x * w.x + a.y * w.y + a.z * w.z + a.w * w.w;
        }
    }
    #pragma unroll
    for (int r = 0; r < 8; r++) {
        acc[r] += __shfl_xor_sync(0xffffffffu, acc[r], 1);
        acc[r] += __shfl_xor_sync(0xffffffffu, acc[r], 2);
    }
    if (part == 0) {
        const float bias = bp[o];
        const int row0 = blockIdx.x * 8;
        #pragma unroll
        for (int r = 0; r < 8; r++) {
            float val = acc[r] + bias;
            if (o < E_) g_q[(size_t)(row0 + r) * E_ + o] = val;
            else        g_k[(size_t)(row0 + r) * E_ + (o - E_)] = val;
        }
    }
}

// ---------------------------------------------------------------------------
// Kernel 2: warp-level HMMA, split across 2 CTAs per i for occupancy.
// CTA (bi, jhalf): D(256x128) = Q[jhalf*256 .. +256)(x32) @ M_i^T(128x32) + C_i
// bf16 3-split (QhMh + QhMl + QlMh), fp32 accum via mma.sync m16n8k8.
// 62KB smem, <=128 regs -> 2 CTAs/SM (16 warps).
// ---------------------------------------------------------------------------
#define ROWB 80   // bytes per padded row (32 bf16 data + pad)
#define JR   256  // j rows per CTA

#define OFF_SK  0                       // 32 f
#define OFF_SC  128                     // 128 f
#define OFF_QH  640                     // 256 * 80
#define OFF_QL  (OFF_QH + JR * ROWB)
#define OFF_MH  (OFF_QL + JR * ROWB)    // 128 * 80
#define OFF_ML  (OFF_MH + 128 * ROWB)
#define SMEM_TOTAL (OFF_ML + 128 * ROWB)  // 62080

__global__ __launch_bounds__(256, 2)
void pair_mma_kernel(const float* __restrict__ Wo,   // [128][64]
                     const float* __restrict__ bo,   // [128]
                     float* __restrict__ out) {      // [B][L][L][P]
    extern __shared__ char smem[];
    float* sK = reinterpret_cast<float*>(smem + OFF_SK);
    float* sC = reinterpret_cast<float*>(smem + OFF_SC);
    char* qh = smem + OFF_QH;
    char* ql = smem + OFF_QL;
    char* mh = smem + OFF_MH;
    char* ml = smem + OFF_ML;

    const int bi    = blockIdx.x >> 1;   // b*L + i
    const int jbase = (blockIdx.x & 1) * JR;
    const int b     = bi >> 9;
    const int tid = threadIdx.x;
    const int wid = tid >> 5;
    const int lid = tid & 31;

    if (tid < E_) sK[tid] = g_k[(size_t)bi * E_ + tid];
    __syncthreads();

    // --- build M (bf16 hi/lo, [p][e]) + C: thread = (p, halfe) ---
    {
        const int p = tid >> 1;
        const int halfe = tid & 1;
        const float* wrow = Wo + (size_t)p * (2 * E_);
        float m[16];
        float cacc = 0.f;
        #pragma unroll
        for (int u = 0; u < 16; u++) {
            const int e = halfe * 16 + u;
            float w1 = wrow[e];
            float w2 = wrow[E_ + e];
            float kv = sK[e];
            m[u] = fmaf(w1, kv, w2);
            cacc += w2 * kv;
        }
        float other = __shfl_xor_sync(0xffffffffu, cacc, 1);
        if (halfe == 0) sC[p] = bo[p] - (cacc + other);

        #pragma unroll
        for (int g = 0; g < 2; g++) {
            uint32_t hw[4], lw[4];
            #pragma unroll
            for (int q = 0; q < 4; q++)
                split2(m[g * 8 + 2 * q], m[g * 8 + 2 * q + 1], hw[q], lw[q]);
            const uint32_t off = (uint32_t)p * ROWB + (uint32_t)halfe * 32u + (uint32_t)g * 16u;
            *reinterpret_cast<uint4*>(mh + off) = make_uint4(hw[0], hw[1], hw[2], hw[3]);
            *reinterpret_cast<uint4*>(ml + off) = make_uint4(lw[0], lw[1], lw[2], lw[3]);
        }
    }

    // --- stage Q chunk (bf16 hi/lo, [j][e]) : 256 rows ---
    {
        const float* qbase = g_q + ((size_t)b * L_ + jbase) * E_;
        #pragma unroll
        for (int it = 0; it < 4; it++) {
            const int idx = tid + 256 * it;           // 0..1023
            const int row = idx >> 2;
            const int grp = idx & 3;                  // e0 = grp*8
            const float4* src = reinterpret_cast<const float4*>(
                qbase + (size_t)row * E_ + grp * 8);
            float4 v0 = src[0];
            float4 v1 = src[1];
            uint32_t hw[4], lw[4];
            split2(v0.x, v0.y, hw[0], lw[0]);
            split2(v0.z, v0.w, hw[1], lw[1]);
            split2(v1.x, v1.y, hw[2], lw[2]);
            split2(v1.z, v1.w, hw[3], lw[3]);
            const uint32_t off = (uint32_t)row * ROWB + (uint32_t)grp * 16u;
            *reinterpret_cast<uint2*>(qh + off)     = make_uint2(hw[0], hw[1]);
            *reinterpret_cast<uint2*>(qh + off + 8) = make_uint2(hw[2], hw[3]);
            *reinterpret_cast<uint2*>(ql + off)     = make_uint2(lw[0], lw[1]);
            *reinterpret_cast<uint2*>(ql + off + 8) = make_uint2(lw[2], lw[3]);
        }
    }

    __syncthreads();

    // --- compute: warp w -> j rows [w*32, w*32+32); loop p-halves of 64 ---
    const int j0 = wid * 32;
    const int g   = lid >> 2;   // groupID 0..7
    const int tig = lid & 3;    // thread-in-group

    const char* Abase[3] = { qh, qh, ql };
    const char* Bbase[3] = { mh, ml, mh };

    #pragma unroll 1
    for (int h = 0; h < 2; h++) {
        float acc[2][8][4];
        #pragma unroll
        for (int mi = 0; mi < 2; mi++)
            #pragma unroll
            for (int ni = 0; ni < 8; ni++)
                #pragma unroll
                for (int q = 0; q < 4; q++) acc[mi][ni][q] = 0.f;

        #pragma unroll
        for (int s = 0; s < 3; s++) {
            const char* A = Abase[s];
            const char* Bb = Bbase[s];
            #pragma unroll
            for (int ks = 0; ks < 4; ks++) {
                const uint32_t kb = (uint32_t)(ks * 8 + 2 * tig) * 2u;  // byte offset of k-pair
                uint32_t a0[2], a1[2];
                #pragma unroll
                for (int mi = 0; mi < 2; mi++) {
                    const uint32_t r = (uint32_t)(j0 + mi * 16 + g);
                    a0[mi] = *reinterpret_cast<const uint32_t*>(A + r * ROWB + kb);
                    a1[mi] = *reinterpret_cast<const uint32_t*>(A + (r + 8) * ROWB + kb);
                }
                uint32_t bb[8];
                #pragma unroll
                for (int ni = 0; ni < 8; ni++) {
                    const uint32_t n = (uint32_t)(h * 64 + ni * 8 + g);
                    bb[ni] = *reinterpret_cast<const uint32_t*>(Bb + n * ROWB + kb);
                }
                #pragma unroll
                for (int mi = 0; mi < 2; mi++)
                    #pragma unroll
                    for (int ni = 0; ni < 8; ni++)
                        mma_bf16(acc[mi][ni][0], acc[mi][ni][1],
                                 acc[mi][ni][2], acc[mi][ni][3],
                                 a0[mi], a1[mi], bb[ni]);
            }
        }

        // --- epilogue: add C, store ---
        #pragma unroll
        for (int mi = 0; mi < 2; mi++) {
            const int j = jbase + j0 + mi * 16 + g;
            float* orow0 = out + (((size_t)bi) * L_ + j) * P_;
            float* orow1 = orow0 + 8 * P_;
            #pragma unroll
            for (int ni = 0; ni < 8; ni++) {
                const int p = h * 64 + ni * 8 + 2 * tig;
                float2 cv = *reinterpret_cast<const float2*>(sC + p);
                float2 o0, o1;
                o0.x = acc[mi][ni][0] + cv.x;
                o0.y = acc[mi][ni][1] + cv.y;
                o1.x = acc[mi][ni][2] + cv.x;
                o1.y = acc[mi][ni][3] + cv.y;
                *reinterpret_cast<float2*>(orow0 + p) = o0;
                *reinterpret_cast<float2*>(orow1 + p) = o1;
            }
        }
    }
}

// ---------------------------------------------------------------------------
// launch
// ---------------------------------------------------------------------------
extern "C" void kernel_launch(void* const* d_in, const int* in_sizes, int n_in,
                              void* d_out, int out_size) {
    const float* seq   = (const float*)d_in[0];
    const float* gamma = (const float*)d_in[1];
    const float* beta  = (const float*)d_in[2];
    const float* Wp    = (const float*)d_in[3];
    const float* bp    = (const float*)d_in[4];
    const float* Wo    = (const float*)d_in[5];
    const float* bo    = (const float*)d_in[6];
    float* out = (float*)d_out;

    static int smem_set = 0;
    if (!smem_set) {
        cudaFuncSetAttribute(pair_mma_kernel,
                             cudaFuncAttributeMaxDynamicSharedMemorySize, SMEM_TOTAL);
        smem_set = 1;
    }

    ln_proj_kernel<<<128, 256>>>(seq, gamma, beta, Wp, bp);
    pair_mma_kernel<<<2 * B_ * L_, 256, SMEM_TOTAL>>>(Wo, bo, out);
}

// round 5
// speedup vs baseline: 1.5536x; 1.1251x over previous
#include <cuda_runtime.h>
#include <cuda_bf16.h>
#include <cstdint>

#define B_  2
#define L_  512
#define D_  1024
#define E_  32      // INNER
#define P_  128     // PAIR

// Scratch for q, k (allocation-free rule: __device__ globals)
__device__ float g_q[B_ * L_ * E_];   // [b*L + j][e]
__device__ float g_k[B_ * L_ * E_];   // [b*L + i][e]

// ---------------------------------------------------------------------------
// helpers
// ---------------------------------------------------------------------------
__device__ __forceinline__ uint32_t smem_u32(const void* p) {
    uint32_t a;
    asm("{ .reg .u64 t; cvta.to.shared.u64 t, %1; cvt.u32.u64 %0, t; }"
        : "=r"(a) : "l"(p));
    return a;
}

__device__ __forceinline__ void mma16(float* d, const uint32_t* a, uint32_t b0, uint32_t b1) {
    asm volatile(
        "mma.sync.aligned.m16n8k16.row.col.f32.bf16.bf16.f32 "
        "{%0,%1,%2,%3}, {%4,%5,%6,%7}, {%8,%9}, {%0,%1,%2,%3};"
        : "+f"(d[0]), "+f"(d[1]), "+f"(d[2]), "+f"(d[3])
        : "r"(a[0]), "r"(a[1]), "r"(a[2]), "r"(a[3]), "r"(b0), "r"(b1));
}

__device__ __forceinline__ void ldsm4(uint32_t* r, uint32_t addr) {
    asm volatile("ldmatrix.sync.aligned.m8n8.x4.shared.b16 {%0,%1,%2,%3}, [%4];"
                 : "=r"(r[0]), "=r"(r[1]), "=r"(r[2]), "=r"(r[3]) : "r"(addr));
}

// bf16 hi/lo split of two floats, packed into two words
__device__ __forceinline__ void split2(float a, float b, uint32_t& hw, uint32_t& lw) {
    __nv_bfloat16 ah = __float2bfloat16(a);
    __nv_bfloat16 bh = __float2bfloat16(b);
    __nv_bfloat16 al = __float2bfloat16(a - __bfloat162float(ah));
    __nv_bfloat16 bl = __float2bfloat16(b - __bfloat162float(bh));
    hw = (uint32_t)__bfloat16_as_ushort(ah) | ((uint32_t)__bfloat16_as_ushort(bh) << 16);
    lw = (uint32_t)__bfloat16_as_ushort(al) | ((uint32_t)__bfloat16_as_ushort(bl) << 16);
}

// ---------------------------------------------------------------------------
// Kernel 1: LayerNorm + projection -> q, k
// grid (128, 2): CTA = 8 rows x 32 outputs (y selects q-half or k-half)
// ---------------------------------------------------------------------------
__global__ __launch_bounds__(256)
void ln_proj_kernel(const float* __restrict__ x,
                    const float* __restrict__ gamma,
                    const float* __restrict__ beta,
                    const float* __restrict__ Wp,   // [64][1024]
                    const float* __restrict__ bp) { // [64]
    const int tid = threadIdx.x;
    const int wid = tid >> 5;
    const int lid = tid & 31;
    const int row = blockIdx.x * 8 + wid;
    const int ohalf = blockIdx.y;       // 0 -> q outs, 1 -> k outs

    __shared__ float sn[8][D_];

    {
        const float4* xr = reinterpret_cast<const float4*>(x + (size_t)row * D_);
        float4 v[8];
        #pragma unroll
        for (int u = 0; u < 8; u++) v[u] = xr[lid + 32 * u];

        float s = 0.f;
        #pragma unroll
        for (int u = 0; u < 8; u++) s += v[u].x + v[u].y + v[u].z + v[u].w;
        #pragma unroll
        for (int o = 16; o > 0; o >>= 1) s += __shfl_xor_sync(0xffffffffu, s, o);
        const float mu = s * (1.0f / D_);

        float ss = 0.f;
        #pragma unroll
        for (int u = 0; u < 8; u++) {
            float d0 = v[u].x - mu, d1 = v[u].y - mu, d2 = v[u].z - mu, d3 = v[u].w - mu;
            ss += d0 * d0 + d1 * d1 + d2 * d2 + d3 * d3;
        }
        #pragma unroll
        for (int o = 16; o > 0; o >>= 1) ss += __shfl_xor_sync(0xffffffffu, ss, o);
        const float rs = rsqrtf(ss * (1.0f / D_) + 1e-5f);

        const float4* g4 = reinterpret_cast<const float4*>(gamma);
        const float4* b4 = reinterpret_cast<const float4*>(beta);
        #pragma unroll
        for (int u = 0; u < 8; u++) {
            float4 g = g4[lid + 32 * u];
            float4 be = b4[lid + 32 * u];
            float4 o4;
            o4.x = (v[u].x - mu) * rs * g.x + be.x;
            o4.y = (v[u].y - mu) * rs * g.y + be.y;
            o4.z = (v[u].z - mu) * rs * g.z + be.z;
            o4.w = (v[u].w - mu) * rs * g.w + be.w;
            reinterpret_cast<float4*>(sn[wid])[lid + 32 * u] = o4;
        }
    }
    __syncthreads();

    // projection: 32 outputs (this half) x 8 rows; thread = (o, part of 8)
    const int o = tid >> 3;           // 0..31
    const int part = tid & 7;         // 0..7
    const int og = ohalf * 32 + o;    // global output index 0..63
    const float4* w4 = reinterpret_cast<const float4*>(Wp + (size_t)og * D_);
    float acc[8];
    #pragma unroll
    for (int r = 0; r < 8; r++) acc[r] = 0.f;

    #pragma unroll 4
    for (int t = 0; t < 32; t++) {
        const int f = part + 8 * t;
        float4 w = w4[f];
        #pragma unroll
        for (int r = 0; r < 8; r++) {
            float4 a = reinterpret_cast<const float4*>(sn[r])[f];
            acc[r] += a.x * w.x + a.y * w.y + a.z * w.z + a.w * w.w;
        }
    }
    #pragma unroll
    for (int r = 0; r < 8; r++) {
        acc[r] += __shfl_xor_sync(0xffffffffu, acc[r], 1);
        acc[r] += __shfl_xor_sync(0xffffffffu, acc[r], 2);
        acc[r] += __shfl_xor_sync(0xffffffffu, acc[r], 4);
    }
    if (part == 0) {
        const float bias = bp[og];
        const int row0 = blockIdx.x * 8;
        float* dst = (ohalf == 0) ? g_q : g_k;
        #pragma unroll
        for (int r = 0; r < 8; r++)
            dst[(size_t)(row0 + r) * E_ + o] = acc[r] + bias;
    }
}

// ---------------------------------------------------------------------------
// Kernel 2: HMMA m16n8k16 + ldmatrix. 2 CTAs per i (256 j rows each).
// D(256x128) = Q_chunk(256x32) @ M_i^T(128x32) + C_i, bf16 3-split.
// ---------------------------------------------------------------------------
#define ROWB 80   // bytes per padded row (32 bf16 data + pad); banks tile perfectly
#define JR   256  // j rows per CTA

#define OFF_SK  0                       // 32 f
#define OFF_SC  128                     // 128 f
#define OFF_QH  640
#define OFF_QL  (OFF_QH + JR * ROWB)
#define OFF_MH  (OFF_QL + JR * ROWB)
#define OFF_ML  (OFF_MH + 128 * ROWB)
#define SMEM_TOTAL (OFF_ML + 128 * ROWB)  // 62080

__global__ __launch_bounds__(256, 2)
void pair_mma_kernel(const float* __restrict__ Wo,   // [128][64]
                     const float* __restrict__ bo,   // [128]
                     float* __restrict__ out) {      // [B][L][L][P]
    extern __shared__ char smem[];
    float* sK = reinterpret_cast<float*>(smem + OFF_SK);
    float* sC = reinterpret_cast<float*>(smem + OFF_SC);

    const uint32_t sbase = smem_u32(smem);

    const int bi    = blockIdx.x >> 1;   // b*L + i
    const int jbase = (blockIdx.x & 1) * JR;
    const int b     = bi >> 9;
    const int tid = threadIdx.x;
    const int wid = tid >> 5;
    const int lid = tid & 31;

    if (tid < E_) sK[tid] = g_k[(size_t)bi * E_ + tid];
    __syncthreads();

    // --- build M (bf16 hi/lo, [p][e]) + C: thread = (p, halfe) ---
    {
        const int p = tid >> 1;
        const int halfe = tid & 1;
        const float* wrow = Wo + (size_t)p * (2 * E_);
        float m[16];
        float cacc = 0.f;
        #pragma unroll
        for (int u = 0; u < 16; u++) {
            const int e = halfe * 16 + u;
            float w1 = wrow[e];
            float w2 = wrow[E_ + e];
            float kv = sK[e];
            m[u] = fmaf(w1, kv, w2);
            cacc += w2 * kv;
        }
        float other = __shfl_xor_sync(0xffffffffu, cacc, 1);
        if (halfe == 0) sC[p] = bo[p] - (cacc + other);

        #pragma unroll
        for (int g = 0; g < 2; g++) {
            uint32_t hw[4], lw[4];
            #pragma unroll
            for (int q = 0; q < 4; q++)
                split2(m[g * 8 + 2 * q], m[g * 8 + 2 * q + 1], hw[q], lw[q]);
            const uint32_t off = (uint32_t)p * ROWB + (uint32_t)halfe * 32u + (uint32_t)g * 16u;
            *reinterpret_cast<uint4*>(smem + OFF_MH + off) = make_uint4(hw[0], hw[1], hw[2], hw[3]);
            *reinterpret_cast<uint4*>(smem + OFF_ML + off) = make_uint4(lw[0], lw[1], lw[2], lw[3]);
        }
    }

    // --- stage Q chunk (bf16 hi/lo, [j][e]) : 256 rows ---
    {
        const float* qbase = g_q + ((size_t)b * L_ + jbase) * E_;
        #pragma unroll
        for (int it = 0; it < 4; it++) {
            const int idx = tid + 256 * it;           // 0..1023
            const int row = idx >> 2;
            const int grp = idx & 3;                  // e0 = grp*8
            const float4* src = reinterpret_cast<const float4*>(
                qbase + (size_t)row * E_ + grp * 8);
            float4 v0 = src[0];
            float4 v1 = src[1];
            uint32_t hw[4], lw[4];
            split2(v0.x, v0.y, hw[0], lw[0]);
            split2(v0.z, v0.w, hw[1], lw[1]);
            split2(v1.x, v1.y, hw[2], lw[2]);
            split2(v1.z, v1.w, hw[3], lw[3]);
            const uint32_t off = (uint32_t)row * ROWB + (uint32_t)grp * 16u;
            *reinterpret_cast<uint2*>(smem + OFF_QH + off)     = make_uint2(hw[0], hw[1]);
            *reinterpret_cast<uint2*>(smem + OFF_QH + off + 8) = make_uint2(hw[2], hw[3]);
            *reinterpret_cast<uint2*>(smem + OFF_QL + off)     = make_uint2(lw[0], lw[1]);
            *reinterpret_cast<uint2*>(smem + OFF_QL + off + 8) = make_uint2(lw[2], lw[3]);
        }
    }

    __syncthreads();

    // --- compute: warp w -> j rows [w*32, +32) ---
    const int j0 = wid * 32;
    const int g   = lid >> 2;   // groupID 0..7
    const int tig = lid & 3;    // thread-in-group

    // ldmatrix per-lane address components
    const int quad   = lid >> 3;
    const int within = lid & 7;
    // A tiles: t0: rows 0-7 k+0 | t1: rows 8-15 k+0 | t2: rows 0-7 k+16 | t3: rows 8-15 k+16
    const uint32_t rowA  = (uint32_t)((quad & 1) * 8 + within);
    const uint32_t koffA = (uint32_t)((quad >> 1) * 16);
    const uint32_t aQH = sbase + OFF_QH + (uint32_t)(j0 + rowA) * ROWB + koffA;
    const uint32_t aQL = sbase + OFF_QL + (uint32_t)(j0 + rowA) * ROWB + koffA;
    // B tiles: t0: n 0-7 k+0 | t1: n 0-7 k+16 | t2: n 8-15 k+0 | t3: n 8-15 k+16
    const uint32_t rowB  = (uint32_t)((quad >> 1) * 8 + within);
    const uint32_t koffB = (uint32_t)((quad & 1) * 16);
    const uint32_t bMH = sbase + OFF_MH + rowB * ROWB + koffB;
    const uint32_t bML = sbase + OFF_ML + rowB * ROWB + koffB;

    #pragma unroll 1
    for (int h = 0; h < 2; h++) {
        float acc[2][8][4];
        #pragma unroll
        for (int mi = 0; mi < 2; mi++)
            #pragma unroll
            for (int ni = 0; ni < 8; ni++)
                #pragma unroll
                for (int q = 0; q < 4; q++) acc[mi][ni][q] = 0.f;

        #pragma unroll
        for (int kc = 0; kc < 2; kc++) {
            uint32_t aqh[2][4], aql[2][4];
            #pragma unroll
            for (int mi = 0; mi < 2; mi++) {
                ldsm4(aqh[mi], aQH + (uint32_t)(mi * 16 * ROWB + kc * 32));
                ldsm4(aql[mi], aQL + (uint32_t)(mi * 16 * ROWB + kc * 32));
            }
            #pragma unroll
            for (int np = 0; np < 4; np++) {
                const uint32_t boff = (uint32_t)((h * 64 + np * 16) * ROWB + kc * 32);
                uint32_t bh[4], bl[4];
                ldsm4(bh, bMH + boff);   // b frags for ni=2np (r0,r1) and ni=2np+1 (r2,r3)
                ldsm4(bl, bML + boff);
                #pragma unroll
                for (int mi = 0; mi < 2; mi++) {
                    #pragma unroll
                    for (int nn = 0; nn < 2; nn++) {
                        float* d = acc[mi][np * 2 + nn];
                        mma16(d, aqh[mi], bh[2 * nn], bh[2 * nn + 1]);  // qh*mh
                        mma16(d, aqh[mi], bl[2 * nn], bl[2 * nn + 1]);  // qh*ml
                        mma16(d, aql[mi], bh[2 * nn], bh[2 * nn + 1]);  // ql*mh
                    }
                }
            }
        }

        // --- epilogue: add C, store ---
        #pragma unroll
        for (int mi = 0; mi < 2; mi++) {
            const int j = jbase + j0 + mi * 16 + g;
            float* orow0 = out + (((size_t)bi) * L_ + j) * P_;
            float* orow1 = orow0 + 8 * P_;
            #pragma unroll
            for (int ni = 0; ni < 8; ni++) {
                const int p = h * 64 + ni * 8 + 2 * tig;
                float2 cv = *reinterpret_cast<const float2*>(sC + p);
                float2 o0, o1;
                o0.x = acc[mi][ni][0] + cv.x;
                o0.y = acc[mi][ni][1] + cv.y;
                o1.x = acc[mi][ni][2] + cv.x;
                o1.y = acc[mi][ni][3] + cv.y;
                *reinterpret_cast<float2*>(orow0 + p) = o0;
                *reinterpret_cast<float2*>(orow1 + p) = o1;
            }
        }
    }
}

// ---------------------------------------------------------------------------
// launch
// ---------------------------------------------------------------------------
extern "C" void kernel_launch(void* const* d_in, const int* in_sizes, int n_in,
                              void* d_out, int out_size) {
    const float* seq   = (const float*)d_in[0];
    const float* gamma = (const float*)d_in[1];
    const float* beta  = (const float*)d_in[2];
    const float* Wp    = (const float*)d_in[3];
    const float* bp    = (const float*)d_in[4];
    const float* Wo    = (const float*)d_in[5];
    const float* bo    = (const float*)d_in[6];
    float* out = (float*)d_out;

    static int smem_set = 0;
    if (!smem_set) {
        cudaFuncSetAttribute(pair_mma_kernel,
                             cudaFuncAttributeMaxDynamicSharedMemorySize, SMEM_TOTAL);
        smem_set = 1;
    }

    ln_proj_kernel<<<dim3(128, 2), 256>>>(seq, gamma, beta, Wp, bp);
    pair_mma_kernel<<<2 * B_ * L_, 256, SMEM_TOTAL>>>(Wo, bo, out);
}

// round 6
// speedup vs baseline: 1.6126x; 1.0380x over previous
#include <cuda_runtime.h>
#include <cuda_bf16.h>
#include <cstdint>

#define B_  2
#define L_  512
#define D_  1024
#define E_  32      // INNER
#define P_  128     // PAIR

// Scratch for q, k (allocation-free rule: __device__ globals)
__device__ float g_q[B_ * L_ * E_];   // [b*L + j][e]
__device__ float g_k[B_ * L_ * E_];   // [b*L + i][e]

// ---------------------------------------------------------------------------
// helpers
// ---------------------------------------------------------------------------
__device__ __forceinline__ uint32_t smem_u32(const void* p) {
    uint32_t a;
    asm("{ .reg .u64 t; cvta.to.shared.u64 t, %1; cvt.u32.u64 %0, t; }"
        : "=r"(a) : "l"(p));
    return a;
}

__device__ __forceinline__ void mma16(float* d, const uint32_t* a, uint32_t b0, uint32_t b1) {
    asm volatile(
        "mma.sync.aligned.m16n8k16.row.col.f32.bf16.bf16.f32 "
        "{%0,%1,%2,%3}, {%4,%5,%6,%7}, {%8,%9}, {%0,%1,%2,%3};"
        : "+f"(d[0]), "+f"(d[1]), "+f"(d[2]), "+f"(d[3])
        : "r"(a[0]), "r"(a[1]), "r"(a[2]), "r"(a[3]), "r"(b0), "r"(b1));
}

__device__ __forceinline__ void ldsm4(uint32_t* r, uint32_t addr) {
    asm volatile("ldmatrix.sync.aligned.m8n8.x4.shared.b16 {%0,%1,%2,%3}, [%4];"
                 : "=r"(r[0]), "=r"(r[1]), "=r"(r[2]), "=r"(r[3]) : "r"(addr));
}

// bf16 hi/lo split of two floats, packed into two words
__device__ __forceinline__ void split2(float a, float b, uint32_t& hw, uint32_t& lw) {
    __nv_bfloat16 ah = __float2bfloat16(a);
    __nv_bfloat16 bh = __float2bfloat16(b);
    __nv_bfloat16 al = __float2bfloat16(a - __bfloat162float(ah));
    __nv_bfloat16 bl = __float2bfloat16(b - __bfloat162float(bh));
    hw = (uint32_t)__bfloat16_as_ushort(ah) | ((uint32_t)__bfloat16_as_ushort(bh) << 16);
    lw = (uint32_t)__bfloat16_as_ushort(al) | ((uint32_t)__bfloat16_as_ushort(bl) << 16);
}

// ---------------------------------------------------------------------------
// Kernel 1: LayerNorm + projection -> q, k
// grid (128, 2): CTA = 8 rows x 32 outputs (y selects q-half or k-half)
// ---------------------------------------------------------------------------
__global__ __launch_bounds__(256)
void ln_proj_kernel(const float* __restrict__ x,
                    const float* __restrict__ gamma,
                    const float* __restrict__ beta,
                    const float* __restrict__ Wp,   // [64][1024]
                    const float* __restrict__ bp) { // [64]
    const int tid = threadIdx.x;
    const int wid = tid >> 5;
    const int lid = tid & 31;
    const int row = blockIdx.x * 8 + wid;
    const int ohalf = blockIdx.y;       // 0 -> q outs, 1 -> k outs

    __shared__ float sn[8][D_];

    {
        const float4* xr = reinterpret_cast<const float4*>(x + (size_t)row * D_);
        float4 v[8];
        #pragma unroll
        for (int u = 0; u < 8; u++) v[u] = xr[lid + 32 * u];

        float s = 0.f;
        #pragma unroll
        for (int u = 0; u < 8; u++) s += v[u].x + v[u].y + v[u].z + v[u].w;
        #pragma unroll
        for (int o = 16; o > 0; o >>= 1) s += __shfl_xor_sync(0xffffffffu, s, o);
        const float mu = s * (1.0f / D_);

        float ss = 0.f;
        #pragma unroll
        for (int u = 0; u < 8; u++) {
            float d0 = v[u].x - mu, d1 = v[u].y - mu, d2 = v[u].z - mu, d3 = v[u].w - mu;
            ss += d0 * d0 + d1 * d1 + d2 * d2 + d3 * d3;
        }
        #pragma unroll
        for (int o = 16; o > 0; o >>= 1) ss += __shfl_xor_sync(0xffffffffu, ss, o);
        const float rs = rsqrtf(ss * (1.0f / D_) + 1e-5f);

        const float4* g4 = reinterpret_cast<const float4*>(gamma);
        const float4* b4 = reinterpret_cast<const float4*>(beta);
        #pragma unroll
        for (int u = 0; u < 8; u++) {
            float4 g = g4[lid + 32 * u];
            float4 be = b4[lid + 32 * u];
            float4 o4;
            o4.x = (v[u].x - mu) * rs * g.x + be.x;
            o4.y = (v[u].y - mu) * rs * g.y + be.y;
            o4.z = (v[u].z - mu) * rs * g.z + be.z;
            o4.w = (v[u].w - mu) * rs * g.w + be.w;
            reinterpret_cast<float4*>(sn[wid])[lid + 32 * u] = o4;
        }
    }
    __syncthreads();

    // projection: 32 outputs (this half) x 8 rows; thread = (o, part of 8)
    const int o = tid >> 3;           // 0..31
    const int part = tid & 7;         // 0..7
    const int og = ohalf * 32 + o;    // global output index 0..63
    const float4* w4 = reinterpret_cast<const float4*>(Wp + (size_t)og * D_);
    float acc[8];
    #pragma unroll
    for (int r = 0; r < 8; r++) acc[r] = 0.f;

    #pragma unroll 4
    for (int t = 0; t < 32; t++) {
        const int f = part + 8 * t;
        float4 w = w4[f];
        #pragma unroll
        for (int r = 0; r < 8; r++) {
            float4 a = reinterpret_cast<const float4*>(sn[r])[f];
            acc[r] += a.x * w.x + a.y * w.y + a.z * w.z + a.w * w.w;
        }
    }
    #pragma unroll
    for (int r = 0; r < 8; r++) {
        acc[r] += __shfl_xor_sync(0xffffffffu, acc[r], 1);
        acc[r] += __shfl_xor_sync(0xffffffffu, acc[r], 2);
        acc[r] += __shfl_xor_sync(0xffffffffu, acc[r], 4);
    }
    if (part == 0) {
        const float bias = bp[og];
        const int row0 = blockIdx.x * 8;
        float* dst = (ohalf == 0) ? g_q : g_k;
        #pragma unroll
        for (int r = 0; r < 8; r++)
            dst[(size_t)(row0 + r) * E_ + o] = acc[r] + bias;
    }
}

// ---------------------------------------------------------------------------
// Kernel 2: HMMA m16n8k16 + ldmatrix, smem-transposed coalesced epilogue.
// 2 CTAs per i (256 j rows each). bf16 3-split, fp32 accum.
// ---------------------------------------------------------------------------
#define ROWB 80    // bytes per padded bf16 row (32 vals + pad)
#define JR   256   // j rows per CTA
#define SROW 72    // staging row stride in floats (conflict-free)

#define OFF_SK  0
#define OFF_SC  128
#define OFF_QH  640
#define OFF_QL  (OFF_QH + JR * ROWB)            // 21120
#define OFF_MH  (OFF_QL + JR * ROWB)            // 41600
#define OFF_ML  (OFF_MH + 128 * ROWB)           // 51840
#define OFF_STG (OFF_ML + 128 * ROWB)           // 62080
#define STG_WARP_F (16 * SROW)                  // 1152 floats per warp
#define SMEM_TOTAL (OFF_STG + 8 * STG_WARP_F * 4)   // 98944

__global__ __launch_bounds__(256, 2)
void pair_mma_kernel(const float* __restrict__ Wo,   // [128][64]
                     const float* __restrict__ bo,   // [128]
                     float* __restrict__ out) {      // [B][L][L][P]
    extern __shared__ char smem[];
    float* sK = reinterpret_cast<float*>(smem + OFF_SK);
    float* sC = reinterpret_cast<float*>(smem + OFF_SC);

    const uint32_t sbase = smem_u32(smem);

    const int bi    = blockIdx.x >> 1;   // b*L + i
    const int jbase = (blockIdx.x & 1) * JR;
    const int b     = bi >> 9;
    const int tid = threadIdx.x;
    const int wid = tid >> 5;
    const int lid = tid & 31;

    if (tid < E_) sK[tid] = g_k[(size_t)bi * E_ + tid];
    __syncthreads();

    // --- build M (bf16 hi/lo, [p][e]) + C: thread = (p, halfe) ---
    {
        const int p = tid >> 1;
        const int halfe = tid & 1;
        const float* wrow = Wo + (size_t)p * (2 * E_);
        float m[16];
        float cacc = 0.f;
        #pragma unroll
        for (int u = 0; u < 16; u++) {
            const int e = halfe * 16 + u;
            float w1 = wrow[e];
            float w2 = wrow[E_ + e];
            float kv = sK[e];
            m[u] = fmaf(w1, kv, w2);
            cacc += w2 * kv;
        }
        float other = __shfl_xor_sync(0xffffffffu, cacc, 1);
        if (halfe == 0) sC[p] = bo[p] - (cacc + other);

        #pragma unroll
        for (int g = 0; g < 2; g++) {
            uint32_t hw[4], lw[4];
            #pragma unroll
            for (int q = 0; q < 4; q++)
                split2(m[g * 8 + 2 * q], m[g * 8 + 2 * q + 1], hw[q], lw[q]);
            const uint32_t off = (uint32_t)p * ROWB + (uint32_t)halfe * 32u + (uint32_t)g * 16u;
            *reinterpret_cast<uint4*>(smem + OFF_MH + off) = make_uint4(hw[0], hw[1], hw[2], hw[3]);
            *reinterpret_cast<uint4*>(smem + OFF_ML + off) = make_uint4(lw[0], lw[1], lw[2], lw[3]);
        }
    }

    // --- stage Q chunk (bf16 hi/lo, [j][e]) : 256 rows ---
    {
        const float* qbase = g_q + ((size_t)b * L_ + jbase) * E_;
        #pragma unroll
        for (int it = 0; it < 4; it++) {
            const int idx = tid + 256 * it;           // 0..1023
            const int row = idx >> 2;
            const int grp = idx & 3;                  // e0 = grp*8
            const float4* src = reinterpret_cast<const float4*>(
                qbase + (size_t)row * E_ + grp * 8);
            float4 v0 = src[0];
            float4 v1 = src[1];
            uint32_t hw[4], lw[4];
            split2(v0.x, v0.y, hw[0], lw[0]);
            split2(v0.z, v0.w, hw[1], lw[1]);
            split2(v1.x, v1.y, hw[2], lw[2]);
            split2(v1.z, v1.w, hw[3], lw[3]);
            const uint32_t off = (uint32_t)row * ROWB + (uint32_t)grp * 16u;
            *reinterpret_cast<uint2*>(smem + OFF_QH + off)     = make_uint2(hw[0], hw[1]);
            *reinterpret_cast<uint2*>(smem + OFF_QH + off + 8) = make_uint2(hw[2], hw[3]);
            *reinterpret_cast<uint2*>(smem + OFF_QL + off)     = make_uint2(lw[0], lw[1]);
            *reinterpret_cast<uint2*>(smem + OFF_QL + off + 8) = make_uint2(lw[2], lw[3]);
        }
    }

    __syncthreads();

    // --- compute: warp w -> j rows [w*32, +32) ---
    const int j0 = wid * 32;
    const int g   = lid >> 2;   // groupID 0..7
    const int tig = lid & 3;    // thread-in-group

    const int quad   = lid >> 3;
    const int within = lid & 7;
    const uint32_t rowA  = (uint32_t)((quad & 1) * 8 + within);
    const uint32_t koffA = (uint32_t)((quad >> 1) * 16);
    const uint32_t aQH = sbase + OFF_QH + (uint32_t)(j0 + rowA) * ROWB + koffA;
    const uint32_t aQL = sbase + OFF_QL + (uint32_t)(j0 + rowA) * ROWB + koffA;
    const uint32_t rowB  = (uint32_t)((quad >> 1) * 8 + within);
    const uint32_t koffB = (uint32_t)((quad & 1) * 16);
    const uint32_t bMH = sbase + OFF_MH + rowB * ROWB + koffB;
    const uint32_t bML = sbase + OFF_ML + rowB * ROWB + koffB;

    float* wbuf = reinterpret_cast<float*>(smem + OFF_STG) + wid * STG_WARP_F;

    #pragma unroll 1
    for (int h = 0; h < 2; h++) {
        float acc[2][8][4];
        #pragma unroll
        for (int mi = 0; mi < 2; mi++)
            #pragma unroll
            for (int ni = 0; ni < 8; ni++)
                #pragma unroll
                for (int q = 0; q < 4; q++) acc[mi][ni][q] = 0.f;

        #pragma unroll
        for (int kc = 0; kc < 2; kc++) {
            uint32_t aqh[2][4], aql[2][4];
            #pragma unroll
            for (int mi = 0; mi < 2; mi++) {
                ldsm4(aqh[mi], aQH + (uint32_t)(mi * 16 * ROWB + kc * 32));
                ldsm4(aql[mi], aQL + (uint32_t)(mi * 16 * ROWB + kc * 32));
            }
            #pragma unroll
            for (int np = 0; np < 4; np++) {
                const uint32_t boff = (uint32_t)((h * 64 + np * 16) * ROWB + kc * 32);
                uint32_t bh[4], bl[4];
                ldsm4(bh, bMH + boff);
                ldsm4(bl, bML + boff);
                #pragma unroll
                for (int mi = 0; mi < 2; mi++) {
                    #pragma unroll
                    for (int nn = 0; nn < 2; nn++) {
                        float* d = acc[mi][np * 2 + nn];
                        mma16(d, aqh[mi], bh[2 * nn], bh[2 * nn + 1]);  // qh*mh
                        mma16(d, aqh[mi], bl[2 * nn], bl[2 * nn + 1]);  // qh*ml
                        mma16(d, aql[mi], bh[2 * nn], bh[2 * nn + 1]);  // ql*mh
                    }
                }
            }
        }

        // --- epilogue: smem transpose -> coalesced STG.128 ---
        #pragma unroll
        for (int mi = 0; mi < 2; mi++) {
            // scatter fragments into private staging (conflict-free)
            #pragma unroll
            for (int ni = 0; ni < 8; ni++) {
                const int col = ni * 8 + 2 * tig;
                *reinterpret_cast<float2*>(&wbuf[g * SROW + col]) =
                    make_float2(acc[mi][ni][0], acc[mi][ni][1]);
                *reinterpret_cast<float2*>(&wbuf[(g + 8) * SROW + col]) =
                    make_float2(acc[mi][ni][2], acc[mi][ni][3]);
            }
            __syncwarp();
            // gather rows + add C + coalesced store (2 rows per pass)
            const int rsub = lid >> 4;           // 0..1
            const int c4i  = lid & 15;           // 0..15 float4 within 64-col half
            const float4 cv = *reinterpret_cast<const float4*>(sC + h * 64 + c4i * 4);
            #pragma unroll
            for (int s = 0; s < 8; s++) {
                const int row = rsub + 2 * s;
                float4 v = *reinterpret_cast<const float4*>(&wbuf[row * SROW + c4i * 4]);
                v.x += cv.x; v.y += cv.y; v.z += cv.z; v.w += cv.w;
                const int j = jbase + j0 + mi * 16 + row;
                float4* dst = reinterpret_cast<float4*>(
                    out + (((size_t)bi) * L_ + j) * P_ + h * 64 + c4i * 4);
                __stcs(dst, v);
            }
            __syncwarp();
        }
    }
}

// ---------------------------------------------------------------------------
// launch
// ---------------------------------------------------------------------------
extern "C" void kernel_launch(void* const* d_in, const int* in_sizes, int n_in,
                              void* d_out, int out_size) {
    const float* seq   = (const float*)d_in[0];
    const float* gamma = (const float*)d_in[1];
    const float* beta  = (const float*)d_in[2];
    const float* Wp    = (const float*)d_in[3];
    const float* bp    = (const float*)d_in[4];
    const float* Wo    = (const float*)d_in[5];
    const float* bo    = (const float*)d_in[6];
    float* out = (float*)d_out;

    static int smem_set = 0;
    if (!smem_set) {
        cudaFuncSetAttribute(pair_mma_kernel,
                             cudaFuncAttributeMaxDynamicSharedMemorySize, SMEM_TOTAL);
        smem_set = 1;
    }

    ln_proj_kernel<<<dim3(128, 2), 256>>>(seq, gamma, beta, Wp, bp);
    pair_mma_kernel<<<2 * B_ * L_, 256, SMEM_TOTAL>>>(Wo, bo, out);
}

// round 7
// speedup vs baseline: 1.6218x; 1.0057x over previous
#include <cuda_runtime.h>
#include <cuda_bf16.h>
#include <cstdint>

#define B_  2
#define L_  512
#define D_  1024
#define E_  32      // INNER
#define P_  128     // PAIR

// Scratch for q, k (allocation-free rule: __device__ globals)
__device__ float g_q[B_ * L_ * E_];   // [b*L + j][e]
__device__ float g_k[B_ * L_ * E_];   // [b*L + i][e]

// ---------------------------------------------------------------------------
// helpers
// ---------------------------------------------------------------------------
__device__ __forceinline__ uint32_t smem_u32(const void* p) {
    uint32_t a;
    asm("{ .reg .u64 t; cvta.to.shared.u64 t, %1; cvt.u32.u64 %0, t; }"
        : "=r"(a) : "l"(p));
    return a;
}

__device__ __forceinline__ void mma16(float* d, const uint32_t* a, uint32_t b0, uint32_t b1) {
    asm volatile(
        "mma.sync.aligned.m16n8k16.row.col.f32.bf16.bf16.f32 "
        "{%0,%1,%2,%3}, {%4,%5,%6,%7}, {%8,%9}, {%0,%1,%2,%3};"
        : "+f"(d[0]), "+f"(d[1]), "+f"(d[2]), "+f"(d[3])
        : "r"(a[0]), "r"(a[1]), "r"(a[2]), "r"(a[3]), "r"(b0), "r"(b1));
}

__device__ __forceinline__ void ldsm4(uint32_t* r, uint32_t addr) {
    asm volatile("ldmatrix.sync.aligned.m8n8.x4.shared.b16 {%0,%1,%2,%3}, [%4];"
                 : "=r"(r[0]), "=r"(r[1]), "=r"(r[2]), "=r"(r[3]) : "r"(addr));
}

// bf16 hi/lo split of two floats, packed into two words
__device__ __forceinline__ void split2(float a, float b, uint32_t& hw, uint32_t& lw) {
    __nv_bfloat16 ah = __float2bfloat16(a);
    __nv_bfloat16 bh = __float2bfloat16(b);
    __nv_bfloat16 al = __float2bfloat16(a - __bfloat162float(ah));
    __nv_bfloat16 bl = __float2bfloat16(b - __bfloat162float(bh));
    hw = (uint32_t)__bfloat16_as_ushort(ah) | ((uint32_t)__bfloat16_as_ushort(bh) << 16);
    lw = (uint32_t)__bfloat16_as_ushort(al) | ((uint32_t)__bfloat16_as_ushort(bl) << 16);
}

// ---------------------------------------------------------------------------
// Kernel 1: LayerNorm + projection -> q, k
// grid (64, 2), 512 threads: CTA = 16 rows x 32 outputs (y: q-half/k-half)
// Single wave (128 CTAs <= 148 SMs); W read once per 16 rows.
// ---------------------------------------------------------------------------
__global__ __launch_bounds__(512)
void ln_proj_kernel(const float* __restrict__ x,
                    const float* __restrict__ gamma,
                    const float* __restrict__ beta,
                    const float* __restrict__ Wp,   // [64][1024]
                    const float* __restrict__ bp) { // [64]
    extern __shared__ float sn[];       // [16][1024]
    const int tid = threadIdx.x;
    const int wid = tid >> 5;
    const int lid = tid & 31;
    const int row = blockIdx.x * 16 + wid;
    const int ohalf = blockIdx.y;       // 0 -> q outs, 1 -> k outs

    {
        const float4* xr = reinterpret_cast<const float4*>(x + (size_t)row * D_);
        float4 v[8];
        #pragma unroll
        for (int u = 0; u < 8; u++) v[u] = xr[lid + 32 * u];

        float s = 0.f;
        #pragma unroll
        for (int u = 0; u < 8; u++) s += v[u].x + v[u].y + v[u].z + v[u].w;
        #pragma unroll
        for (int o = 16; o > 0; o >>= 1) s += __shfl_xor_sync(0xffffffffu, s, o);
        const float mu = s * (1.0f / D_);

        float ss = 0.f;
        #pragma unroll
        for (int u = 0; u < 8; u++) {
            float d0 = v[u].x - mu, d1 = v[u].y - mu, d2 = v[u].z - mu, d3 = v[u].w - mu;
            ss += d0 * d0 + d1 * d1 + d2 * d2 + d3 * d3;
        }
        #pragma unroll
        for (int o = 16; o > 0; o >>= 1) ss += __shfl_xor_sync(0xffffffffu, ss, o);
        const float rs = rsqrtf(ss * (1.0f / D_) + 1e-5f);

        const float4* g4 = reinterpret_cast<const float4*>(gamma);
        const float4* b4 = reinterpret_cast<const float4*>(beta);
        #pragma unroll
        for (int u = 0; u < 8; u++) {
            float4 g = g4[lid + 32 * u];
            float4 be = b4[lid + 32 * u];
            float4 o4;
            o4.x = (v[u].x - mu) * rs * g.x + be.x;
            o4.y = (v[u].y - mu) * rs * g.y + be.y;
            o4.z = (v[u].z - mu) * rs * g.z + be.z;
            o4.w = (v[u].w - mu) * rs * g.w + be.w;
            reinterpret_cast<float4*>(sn + (size_t)wid * D_)[lid + 32 * u] = o4;
        }
    }
    __syncthreads();

    // projection: 32 outputs (this half) x 16 rows; thread = (o, part of 16)
    const int o = tid >> 4;           // 0..31
    const int part = tid & 15;        // 0..15
    const int og = ohalf * 32 + o;    // global output index 0..63
    const float4* w4 = reinterpret_cast<const float4*>(Wp + (size_t)og * D_);
    float acc[16];
    #pragma unroll
    for (int r = 0; r < 16; r++) acc[r] = 0.f;

    #pragma unroll 4
    for (int t = 0; t < 16; t++) {
        const int f = part + 16 * t;
        float4 w = w4[f];
        #pragma unroll
        for (int r = 0; r < 16; r++) {
            float4 a = reinterpret_cast<const float4*>(sn + (size_t)r * D_)[f];
            acc[r] += a.x * w.x + a.y * w.y + a.z * w.z + a.w * w.w;
        }
    }
    #pragma unroll
    for (int r = 0; r < 16; r++) {
        acc[r] += __shfl_xor_sync(0xffffffffu, acc[r], 1);
        acc[r] += __shfl_xor_sync(0xffffffffu, acc[r], 2);
        acc[r] += __shfl_xor_sync(0xffffffffu, acc[r], 4);
        acc[r] += __shfl_xor_sync(0xffffffffu, acc[r], 8);
    }
    if (part == 0) {
        const float bias = bp[og];
        const int row0 = blockIdx.x * 16;
        float* dst = (ohalf == 0) ? g_q : g_k;
        #pragma unroll
        for (int r = 0; r < 16; r++)
            dst[(size_t)(row0 + r) * E_ + o] = acc[r] + bias;
    }
}

// ---------------------------------------------------------------------------
// Kernel 2: HMMA m16n8k16 + ldmatrix, smem-transposed coalesced epilogue.
// 2 CTAs per i (256 j rows each). bf16 3-split, fp32 accum.
// A fragments hoisted out of the h loop (h-invariant).
// ---------------------------------------------------------------------------
#define ROWB 80    // bytes per padded bf16 row (32 vals + pad)
#define JR   256   // j rows per CTA
#define SROW 72    // staging row stride in floats

#define OFF_SK  0
#define OFF_SC  128
#define OFF_QH  640
#define OFF_QL  (OFF_QH + JR * ROWB)            // 21120
#define OFF_MH  (OFF_QL + JR * ROWB)            // 41600
#define OFF_ML  (OFF_MH + 128 * ROWB)           // 51840
#define OFF_STG (OFF_ML + 128 * ROWB)           // 62080
#define STG_WARP_F (16 * SROW)                  // 1152 floats per warp
#define SMEM_TOTAL (OFF_STG + 8 * STG_WARP_F * 4)   // 98944

__global__ __launch_bounds__(256, 2)
void pair_mma_kernel(const float* __restrict__ Wo,   // [128][64]
                     const float* __restrict__ bo,   // [128]
                     float* __restrict__ out) {      // [B][L][L][P]
    extern __shared__ char smem[];
    float* sK = reinterpret_cast<float*>(smem + OFF_SK);
    float* sC = reinterpret_cast<float*>(smem + OFF_SC);

    const uint32_t sbase = smem_u32(smem);

    const int bi    = blockIdx.x >> 1;   // b*L + i
    const int jbase = (blockIdx.x & 1) * JR;
    const int b     = bi >> 9;
    const int tid = threadIdx.x;
    const int wid = tid >> 5;
    const int lid = tid & 31;

    if (tid < E_) sK[tid] = g_k[(size_t)bi * E_ + tid];
    __syncthreads();

    // --- build M (bf16 hi/lo, [p][e]) + C: thread = (p, halfe) ---
    {
        const int p = tid >> 1;
        const int halfe = tid & 1;
        const float* wrow = Wo + (size_t)p * (2 * E_);
        float m[16];
        float cacc = 0.f;
        #pragma unroll
        for (int u = 0; u < 16; u++) {
            const int e = halfe * 16 + u;
            float w1 = wrow[e];
            float w2 = wrow[E_ + e];
            float kv = sK[e];
            m[u] = fmaf(w1, kv, w2);
            cacc += w2 * kv;
        }
        float other = __shfl_xor_sync(0xffffffffu, cacc, 1);
        if (halfe == 0) sC[p] = bo[p] - (cacc + other);

        #pragma unroll
        for (int g = 0; g < 2; g++) {
            uint32_t hw[4], lw[4];
            #pragma unroll
            for (int q = 0; q < 4; q++)
                split2(m[g * 8 + 2 * q], m[g * 8 + 2 * q + 1], hw[q], lw[q]);
            const uint32_t off = (uint32_t)p * ROWB + (uint32_t)halfe * 32u + (uint32_t)g * 16u;
            *reinterpret_cast<uint4*>(smem + OFF_MH + off) = make_uint4(hw[0], hw[1], hw[2], hw[3]);
            *reinterpret_cast<uint4*>(smem + OFF_ML + off) = make_uint4(lw[0], lw[1], lw[2], lw[3]);
        }
    }

    // --- stage Q chunk (bf16 hi/lo, [j][e]) : 256 rows, STS.128 packed ---
    {
        const float* qbase = g_q + ((size_t)b * L_ + jbase) * E_;
        #pragma unroll
        for (int it = 0; it < 4; it++) {
            const int idx = tid + 256 * it;           // 0..1023
            const int row = idx >> 2;
            const int grp = idx & 3;                  // e0 = grp*8
            const float4* src = reinterpret_cast<const float4*>(
                qbase + (size_t)row * E_ + grp * 8);
            float4 v0 = src[0];
            float4 v1 = src[1];
            uint32_t hw[4], lw[4];
            split2(v0.x, v0.y, hw[0], lw[0]);
            split2(v0.z, v0.w, hw[1], lw[1]);
            split2(v1.x, v1.y, hw[2], lw[2]);
            split2(v1.z, v1.w, hw[3], lw[3]);
            const uint32_t off = (uint32_t)row * ROWB + (uint32_t)grp * 16u;
            *reinterpret_cast<uint4*>(smem + OFF_QH + off) = make_uint4(hw[0], hw[1], hw[2], hw[3]);
            *reinterpret_cast<uint4*>(smem + OFF_QL + off) = make_uint4(lw[0], lw[1], lw[2], lw[3]);
        }
    }

    __syncthreads();

    // --- compute: warp w -> j rows [w*32, +32) ---
    const int j0 = wid * 32;
    const int g   = lid >> 2;   // groupID 0..7
    const int tig = lid & 3;    // thread-in-group

    const int quad   = lid >> 3;
    const int within = lid & 7;
    const uint32_t rowA  = (uint32_t)((quad & 1) * 8 + within);
    const uint32_t koffA = (uint32_t)((quad >> 1) * 16);
    const uint32_t aQH = sbase + OFF_QH + (uint32_t)(j0 + rowA) * ROWB + koffA;
    const uint32_t aQL = sbase + OFF_QL + (uint32_t)(j0 + rowA) * ROWB + koffA;
    const uint32_t rowB  = (uint32_t)((quad >> 1) * 8 + within);
    const uint32_t koffB = (uint32_t)((quad & 1) * 16);
    const uint32_t bMH = sbase + OFF_MH + rowB * ROWB + koffB;
    const uint32_t bML = sbase + OFF_ML + rowB * ROWB + koffB;

    float* wbuf = reinterpret_cast<float*>(smem + OFF_STG) + wid * STG_WARP_F;

    // A fragments are h-invariant: load once.  [kc][mi][4]
    uint32_t aqh[2][2][4], aql[2][2][4];
    #pragma unroll
    for (int kc = 0; kc < 2; kc++)
        #pragma unroll
        for (int mi = 0; mi < 2; mi++) {
            ldsm4(aqh[kc][mi], aQH + (uint32_t)(mi * 16 * ROWB + kc * 32));
            ldsm4(aql[kc][mi], aQL + (uint32_t)(mi * 16 * ROWB + kc * 32));
        }

    #pragma unroll 1
    for (int h = 0; h < 2; h++) {
        float acc[2][8][4];
        #pragma unroll
        for (int mi = 0; mi < 2; mi++)
            #pragma unroll
            for (int ni = 0; ni < 8; ni++)
                #pragma unroll
                for (int q = 0; q < 4; q++) acc[mi][ni][q] = 0.f;

        #pragma unroll
        for (int kc = 0; kc < 2; kc++) {
            #pragma unroll
            for (int np = 0; np < 4; np++) {
                const uint32_t boff = (uint32_t)((h * 64 + np * 16) * ROWB + kc * 32);
                uint32_t bh[4], bl[4];
                ldsm4(bh, bMH + boff);
                ldsm4(bl, bML + boff);
                #pragma unroll
                for (int mi = 0; mi < 2; mi++) {
                    #pragma unroll
                    for (int nn = 0; nn < 2; nn++) {
                        float* d = acc[mi][np * 2 + nn];
                        mma16(d, aqh[kc][mi], bh[2 * nn], bh[2 * nn + 1]);  // qh*mh
                        mma16(d, aqh[kc][mi], bl[2 * nn], bl[2 * nn + 1]);  // qh*ml
                        mma16(d, aql[kc][mi], bh[2 * nn], bh[2 * nn + 1]);  // ql*mh
                    }
                }
            }
        }

        // --- epilogue: smem transpose -> coalesced STG.128 ---
        #pragma unroll
        for (int mi = 0; mi < 2; mi++) {
            #pragma unroll
            for (int ni = 0; ni < 8; ni++) {
                const int col = ni * 8 + 2 * tig;
                *reinterpret_cast<float2*>(&wbuf[g * SROW + col]) =
                    make_float2(acc[mi][ni][0], acc[mi][ni][1]);
                *reinterpret_cast<float2*>(&wbuf[(g + 8) * SROW + col]) =
                    make_float2(acc[mi][ni][2], acc[mi][ni][3]);
            }
            __syncwarp();
            const int rsub = lid >> 4;           // 0..1
            const int c4i  = lid & 15;           // 0..15 float4 within 64-col half
            const float4 cv = *reinterpret_cast<const float4*>(sC + h * 64 + c4i * 4);
            #pragma unroll
            for (int s = 0; s < 8; s++) {
                const int row = rsub + 2 * s;
                float4 v = *reinterpret_cast<const float4*>(&wbuf[row * SROW + c4i * 4]);
                v.x += cv.x; v.y += cv.y; v.z += cv.z; v.w += cv.w;
                const int j = jbase + j0 + mi * 16 + row;
                float4* dst = reinterpret_cast<float4*>(
                    out + (((size_t)bi) * L_ + j) * P_ + h * 64 + c4i * 4);
                __stcs(dst, v);
            }
            __syncwarp();
        }
    }
}

// ---------------------------------------------------------------------------
// launch
// ---------------------------------------------------------------------------
extern "C" void kernel_launch(void* const* d_in, const int* in_sizes, int n_in,
                              void* d_out, int out_size) {
    const float* seq   = (const float*)d_in[0];
    const float* gamma = (const float*)d_in[1];
    const float* beta  = (const float*)d_in[2];
    const float* Wp    = (const float*)d_in[3];
    const float* bp    = (const float*)d_in[4];
    const float* Wo    = (const float*)d_in[5];
    const float* bo    = (const float*)d_in[6];
    float* out = (float*)d_out;

    static int smem_set = 0;
    if (!smem_set) {
        cudaFuncSetAttribute(pair_mma_kernel,
                             cudaFuncAttributeMaxDynamicSharedMemorySize, SMEM_TOTAL);
        cudaFuncSetAttribute(ln_proj_kernel,
                             cudaFuncAttributeMaxDynamicSharedMemorySize, 16 * D_ * 4);
        smem_set = 1;
    }

    ln_proj_kernel<<<dim3(64, 2), 512, 16 * D_ * 4>>>(seq, gamma, beta, Wp, bp);
    pair_mma_kernel<<<2 * B_ * L_, 256, SMEM_TOTAL>>>(Wo, bo, out);
}